// round 2
// baseline (speedup 1.0000x reference)
#include <cuda_runtime.h>
#include <math.h>

#define NQ       12
#define DEPTH    4
#define DIM      4096
#define NTHREADS 256

typedef unsigned long long u64;

// ---- packed f32x2 helpers (sm_100+ PTX) ----
__device__ __forceinline__ u64 pk(float lo, float hi) {
    u64 r; asm("mov.b64 %0, {%1, %2};" : "=l"(r) : "f"(lo), "f"(hi)); return r;
}
__device__ __forceinline__ void upk(u64 v, float& lo, float& hi) {
    asm("mov.b64 {%0, %1}, %2;" : "=f"(lo), "=f"(hi) : "l"(v));
}
__device__ __forceinline__ u64 swp(u64 v) {   // (x,y) -> (y,x)
    float x, y; asm("mov.b64 {%0, %1}, %2;" : "=f"(x), "=f"(y) : "l"(v));
    u64 r; asm("mov.b64 %0, {%1, %2};" : "=l"(r) : "f"(y), "f"(x)); return r;
}
__device__ __forceinline__ u64 f2fma(u64 a, u64 b, u64 c) {
    u64 d; asm("fma.rn.f32x2 %0, %1, %2, %3;" : "=l"(d) : "l"(a), "l"(b), "l"(c)); return d;
}
__device__ __forceinline__ u64 f2mul(u64 a, u64 b) {
    u64 d; asm("mul.rn.f32x2 %0, %1, %2;" : "=l"(d) : "l"(a), "l"(b)); return d;
}

// XOR swizzle for conflict-free 8B shared accesses
__device__ __forceinline__ int swz(int e) { return e ^ ((e >> 4) & 15); }

// Composed CNOT-ladder gather: s_after[i] = s_before[gperm(i)].
__device__ __forceinline__ int gperm(int j) {
    j ^= (j & 1) << 11;                 // m = 11: CNOT(q11 -> q0)
    #pragma unroll
    for (int m = 10; m >= 0; --m)
        j ^= ((j >> (11 - m)) & 1) << (10 - m);
    return j;
}

// Apply fused 2x2 complex gate to register-local bit k.
// Amp r packed as (re, im). Gate g = 8 packed coeffs:
//   [c00, d00, c01, d01, c10, d10, c11, d11], c=(ur,ur), d=(-ui,ui)
// complex u*a = fma(c, a, mul(d, swap(a)))
__device__ __forceinline__ void apply_gate(u64 v[16], const u64* __restrict__ g, int k) {
    const u64 c00 = g[0], d00 = g[1], c01 = g[2], d01 = g[3];
    const u64 c10 = g[4], d10 = g[5], c11 = g[6], d11 = g[7];
    const int m = 1 << k;
    #pragma unroll
    for (int r0 = 0; r0 < 16; ++r0) {
        if (r0 & m) continue;
        const int r1 = r0 | m;
        const u64 a0 = v[r0], a1 = v[r1];
        const u64 a0s = swp(a0), a1s = swp(a1);
        u64 t0 = f2mul(d01, a1s);
        t0 = f2fma(c01, a1, t0);
        t0 = f2fma(d00, a0s, t0);
        v[r0] = f2fma(c00, a0, t0);
        u64 t1 = f2mul(d11, a1s);
        t1 = f2fma(c11, a1, t1);
        t1 = f2fma(d10, a0s, t1);
        v[r1] = f2fma(c10, a0, t1);
    }
}

__global__ void __launch_bounds__(NTHREADS)
qsim_kernel(const float* __restrict__ input,
            const float* __restrict__ ax,
            const float* __restrict__ ay,
            const float* __restrict__ az,
            float* __restrict__ out)
{
    __shared__ u64   sAmp[DIM];               // 32 KB state exchange buffer
    __shared__ u64   sGates[DEPTH * NQ * 8];  // 48 gates x 8 packed coeffs = 3 KB
    __shared__ float sRed[16];

    const int tid = threadIdx.x;
    const int row = blockIdx.x;

    // ---- fused gate matrices U = Rz * Ry * Rx, packed-coefficient form ----
    if (tid < DEPTH * NQ) {
        float sx, cx, sy, cy, sz, cz;
        sincosf(0.5f * ax[tid], &sx, &cx);
        sincosf(0.5f * ay[tid], &sy, &cy);
        sincosf(0.5f * az[tid], &sz, &cz);
        // M = Ry*Rx
        const float m00r = cy * cx, m00i =  sy * sx;
        const float m01r = -sy * cx, m01i = -cy * sx;
        const float m10r =  sy * cx, m10i = -cy * sx;
        const float m11r =  cy * cx, m11i = -sy * sx;
        // U row0 = exp(-i lz/2) * M row0 ; U row1 = exp(+i lz/2) * M row1
        const float u00r = cz * m00r + sz * m00i, u00i = cz * m00i - sz * m00r;
        const float u01r = cz * m01r + sz * m01i, u01i = cz * m01i - sz * m01r;
        const float u10r = cz * m10r - sz * m10i, u10i = cz * m10i + sz * m10r;
        const float u11r = cz * m11r - sz * m11i, u11i = cz * m11i + sz * m11r;
        u64* g = &sGates[tid * 8];
        g[0] = pk(u00r, u00r);  g[1] = pk(-u00i, u00i);
        g[2] = pk(u01r, u01r);  g[3] = pk(-u01i, u01i);
        g[4] = pk(u10r, u10r);  g[5] = pk(-u10i, u10i);
        g[6] = pk(u11r, u11r);  g[7] = pk(-u11i, u11i);
    }

    // ---- load input row + amplitude encoding ----
    float mag[16];
    const float4* inrow = reinterpret_cast<const float4*>(input + (size_t)row * DIM);
    float s1 = 0.f, s2 = 0.f;
    #pragma unroll
    for (int k = 0; k < 4; ++k) {
        const float4 w = inrow[tid * 4 + k];
        const float a = fabsf(w.x), b = fabsf(w.y), c = fabsf(w.z), d = fabsf(w.w);
        mag[4 * k + 0] = a; mag[4 * k + 1] = b;
        mag[4 * k + 2] = c; mag[4 * k + 3] = d;
        s1 += (a + b) + (c + d);
        s2 += a * a + b * b + c * c + d * d;
    }
    #pragma unroll
    for (int o = 16; o > 0; o >>= 1) {
        s1 += __shfl_xor_sync(0xffffffffu, s1, o);
        s2 += __shfl_xor_sync(0xffffffffu, s2, o);
    }
    if ((tid & 31) == 0) { sRed[tid >> 5] = s1; sRed[8 + (tid >> 5)] = s2; }
    __syncthreads();   // also publishes sGates
    float S1 = 0.f, S2 = 0.f;
    #pragma unroll
    for (int w = 0; w < 8; ++w) { S1 += sRed[w]; S2 += sRed[8 + w]; }

    // state: thread t holds flat indices [t*16, t*16+16) (Layout0), amp = (re,im) packed
    u64 v[16];
    if (S1 > 1e-8f) {
        const float sc   = rsqrtf(S1);
        const float norm = sqrtf(S2) * sc;
        const float fs   = (norm > 1e-8f) ? (sc / norm) : sc;
        #pragma unroll
        for (int r = 0; r < 16; ++r) v[r] = pk(mag[r] * fs, 0.f);
    } else {
        #pragma unroll
        for (int r = 0; r < 16; ++r) v[r] = pk(0.015625f, 0.f);
    }

    const int t = tid;

    #pragma unroll 1
    for (int layer = 0; layer < DEPTH; ++layer) {
        const u64* gl = &sGates[layer * NQ * 8];

        // ---- Stage A (Layout0): reg bit k == global bit k -> qubit 11-k ----
        #pragma unroll
        for (int k = 0; k < 4; ++k) apply_gate(v, gl + (11 - k) * 8, k);

        // ---- Layout0 -> Layout1 ----
        __syncthreads();
        #pragma unroll
        for (int r = 0; r < 16; ++r) sAmp[swz((t << 4) | r)] = v[r];
        __syncthreads();
        {
            const int base = ((t >> 4) << 8) | (t & 15);
            #pragma unroll
            for (int r = 0; r < 16; ++r) v[r] = sAmp[swz(base | (r << 4))];
        }

        // ---- Stage B: reg bit k == global bit 4+k -> qubit 7-k ----
        #pragma unroll
        for (int k = 0; k < 4; ++k) apply_gate(v, gl + (7 - k) * 8, k);

        // ---- Layout1 -> Layout2 ----
        __syncthreads();
        {
            const int base = ((t >> 4) << 8) | (t & 15);
            #pragma unroll
            for (int r = 0; r < 16; ++r) sAmp[swz(base | (r << 4))] = v[r];
        }
        __syncthreads();
        #pragma unroll
        for (int r = 0; r < 16; ++r) v[r] = sAmp[swz((r << 8) | t)];

        // ---- Stage C: reg bit k == global bit 8+k -> qubit 3-k ----
        #pragma unroll
        for (int k = 0; k < 4; ++k) apply_gate(v, gl + (3 - k) * 8, k);

        // ---- Layout2 -> Layout0, CNOT ladder folded into the gather ----
        __syncthreads();
        #pragma unroll
        for (int r = 0; r < 16; ++r) sAmp[swz((r << 8) | t)] = v[r];
        __syncthreads();
        #pragma unroll
        for (int r = 0; r < 16; ++r) v[r] = sAmp[swz(gperm((t << 4) | r))];
    }

    // ---- measurement: |amplitude| ----
    float4* orow = reinterpret_cast<float4*>(out + (size_t)row * DIM);
    #pragma unroll
    for (int k = 0; k < 4; ++k) {
        float xr, xi;
        float4 o;
        upk(v[4 * k + 0], xr, xi); o.x = sqrtf(xr * xr + xi * xi);
        upk(v[4 * k + 1], xr, xi); o.y = sqrtf(xr * xr + xi * xi);
        upk(v[4 * k + 2], xr, xi); o.z = sqrtf(xr * xr + xi * xi);
        upk(v[4 * k + 3], xr, xi); o.w = sqrtf(xr * xr + xi * xi);
        orow[tid * 4 + k] = o;
    }
}

extern "C" void kernel_launch(void* const* d_in, const int* in_sizes, int n_in,
                              void* d_out, int out_size) {
    const float* input = (const float*)d_in[0];
    const float* ax    = (const float*)d_in[1];
    const float* ay    = (const float*)d_in[2];
    const float* az    = (const float*)d_in[3];
    float* out = (float*)d_out;
    const int rows = in_sizes[0] / DIM;
    qsim_kernel<<<rows, NTHREADS>>>(input, ax, ay, az, out);
}

// round 3
// speedup vs baseline: 1.2157x; 1.2157x over previous
#include <cuda_runtime.h>
#include <math.h>

#define NQ       12
#define DEPTH    4
#define DIM      4096
#define NTHREADS 256

// XOR swizzle for conflict-free float2 shared accesses
__device__ __forceinline__ int swz(int e) { return e ^ ((e >> 4) & 15); }

// Closed-form composed CNOT-ladder gather: s_after[i] = s_before[gperm(i)].
// Equivalent to: j ^= (j&1)<<11; for m=10..0: j ^= ((j>>(11-m))&1)<<(10-m);
__device__ __forceinline__ int gperm(int j) {
    return j ^ (j >> 1) ^ ((j & 1) ? 0xC00 : 0);
}

// Fused 2x2 complex gate on register-local bit k of the 16-amp register file.
__device__ __forceinline__ void apply_gate(float re[16], float im[16],
                                           const float* __restrict__ g, int k) {
    const float u00r = g[0], u00i = g[1], u01r = g[2], u01i = g[3];
    const float u10r = g[4], u10i = g[5], u11r = g[6], u11i = g[7];
    const int m = 1 << k;
    #pragma unroll
    for (int r0 = 0; r0 < 16; ++r0) {
        if (r0 & m) continue;
        const int r1 = r0 | m;
        const float a0r = re[r0], a0i = im[r0];
        const float a1r = re[r1], a1i = im[r1];
        re[r0] = u00r * a0r - u00i * a0i + u01r * a1r - u01i * a1i;
        im[r0] = u00r * a0i + u00i * a0r + u01r * a1i + u01i * a1r;
        re[r1] = u10r * a0r - u10i * a0i + u11r * a1r - u11i * a1i;
        im[r1] = u10r * a0i + u10i * a0r + u11r * a1i + u11i * a1r;
    }
}

// Same gate but input state is purely real (im == 0): half the FMAs.
__device__ __forceinline__ void apply_gate_real(float re[16], float im[16],
                                                const float* __restrict__ g, int k) {
    const float u00r = g[0], u00i = g[1], u01r = g[2], u01i = g[3];
    const float u10r = g[4], u10i = g[5], u11r = g[6], u11i = g[7];
    const int m = 1 << k;
    #pragma unroll
    for (int r0 = 0; r0 < 16; ++r0) {
        if (r0 & m) continue;
        const int r1 = r0 | m;
        const float a0r = re[r0], a1r = re[r1];
        re[r0] = u00r * a0r + u01r * a1r;
        im[r0] = u00i * a0r + u01i * a1r;
        re[r1] = u10r * a0r + u11r * a1r;
        im[r1] = u10i * a0r + u11i * a1r;
    }
}

__global__ void __launch_bounds__(NTHREADS, 2)
qsim_kernel(const float* __restrict__ input,
            const float* __restrict__ ax,
            const float* __restrict__ ay,
            const float* __restrict__ az,
            float* __restrict__ out)
{
    extern __shared__ float2 sDyn[];          // 2 x 32 KB ping-pong exchange buffers
    float2* bufA = sDyn;
    float2* bufB = sDyn + DIM;

    __shared__ float sGates[DEPTH * NQ * 8];  // 48 fused gates, 8 floats each
    __shared__ float sRed[16];

    const int tid = threadIdx.x;
    const int row = blockIdx.x;

    // ---- fused gate matrices U = Rz * Ry * Rx ----
    if (tid < DEPTH * NQ) {
        float sx, cx, sy, cy, sz, cz;
        sincosf(0.5f * ax[tid], &sx, &cx);
        sincosf(0.5f * ay[tid], &sy, &cy);
        sincosf(0.5f * az[tid], &sz, &cz);
        const float m00r = cy * cx, m00i =  sy * sx;
        const float m01r = -sy * cx, m01i = -cy * sx;
        const float m10r =  sy * cx, m10i = -cy * sx;
        const float m11r =  cy * cx, m11i = -sy * sx;
        float* g = &sGates[tid * 8];
        g[0] = cz * m00r + sz * m00i;  g[1] = cz * m00i - sz * m00r;
        g[2] = cz * m01r + sz * m01i;  g[3] = cz * m01i - sz * m01r;
        g[4] = cz * m10r - sz * m10i;  g[5] = cz * m10i + sz * m10r;
        g[6] = cz * m11r - sz * m11i;  g[7] = cz * m11i + sz * m11r;
    }

    // ---- load input row + amplitude encoding ----
    float mag[16];
    const float4* inrow = reinterpret_cast<const float4*>(input + (size_t)row * DIM);
    float s1 = 0.f, s2 = 0.f;
    #pragma unroll
    for (int k = 0; k < 4; ++k) {
        const float4 v = inrow[tid * 4 + k];
        const float a = fabsf(v.x), b = fabsf(v.y), c = fabsf(v.z), d = fabsf(v.w);
        mag[4 * k + 0] = a; mag[4 * k + 1] = b;
        mag[4 * k + 2] = c; mag[4 * k + 3] = d;
        s1 += (a + b) + (c + d);
        s2 += a * a + b * b + c * c + d * d;
    }
    #pragma unroll
    for (int o = 16; o > 0; o >>= 1) {
        s1 += __shfl_xor_sync(0xffffffffu, s1, o);
        s2 += __shfl_xor_sync(0xffffffffu, s2, o);
    }
    if ((tid & 31) == 0) { sRed[tid >> 5] = s1; sRed[8 + (tid >> 5)] = s2; }
    __syncthreads();   // also publishes sGates
    float S1 = 0.f, S2 = 0.f;
    #pragma unroll
    for (int w = 0; w < 8; ++w) { S1 += sRed[w]; S2 += sRed[8 + w]; }

    // state: thread t holds flat indices [t*16, t*16+16) (Layout0)
    float re[16], im[16];
    if (S1 > 1e-8f) {
        const float sc   = rsqrtf(S1);
        const float norm = sqrtf(S2) * sc;
        const float fs   = (norm > 1e-8f) ? (sc / norm) : sc;
        #pragma unroll
        for (int r = 0; r < 16; ++r) { re[r] = mag[r] * fs; im[r] = 0.f; }
    } else {
        #pragma unroll
        for (int r = 0; r < 16; ++r) { re[r] = 0.015625f; im[r] = 0.f; }
    }

    const int t = tid;

    #pragma unroll 1
    for (int layer = 0; layer < DEPTH; ++layer) {
        const float* gl = &sGates[layer * NQ * 8];

        // ---- Stage A (Layout0): reg bit k == global bit k -> qubit 11-k ----
        if (layer == 0) {
            // state is purely real at entry
            apply_gate_real(re, im, gl + 11 * 8, 0);
            #pragma unroll
            for (int k = 1; k < 4; ++k) apply_gate(re, im, gl + (11 - k) * 8, k);
        } else {
            #pragma unroll
            for (int k = 0; k < 4; ++k) apply_gate(re, im, gl + (11 - k) * 8, k);
        }

        // ---- E1: Layout0 -> Layout1 (buffer A) ----
        #pragma unroll
        for (int r = 0; r < 16; ++r)
            bufA[swz((t << 4) | r)] = make_float2(re[r], im[r]);
        __syncthreads();
        {
            const int base = ((t >> 4) << 8) | (t & 15);
            #pragma unroll
            for (int r = 0; r < 16; ++r) {
                const float2 v = bufA[swz(base | (r << 4))];
                re[r] = v.x; im[r] = v.y;
            }
        }

        // ---- Stage B: reg bit k == global bit 4+k -> qubit 7-k ----
        #pragma unroll
        for (int k = 0; k < 4; ++k) apply_gate(re, im, gl + (7 - k) * 8, k);

        // ---- E2: Layout1 -> Layout2 (buffer B) ----
        {
            const int base = ((t >> 4) << 8) | (t & 15);
            #pragma unroll
            for (int r = 0; r < 16; ++r)
                bufB[swz(base | (r << 4))] = make_float2(re[r], im[r]);
        }
        __syncthreads();
        #pragma unroll
        for (int r = 0; r < 16; ++r) {
            const float2 v = bufB[swz((r << 8) | t)];
            re[r] = v.x; im[r] = v.y;
        }

        // ---- Stage C: reg bit k == global bit 8+k -> qubit 3-k ----
        #pragma unroll
        for (int k = 0; k < 4; ++k) apply_gate(re, im, gl + (3 - k) * 8, k);

        // ---- E3: Layout2 -> Layout0 with CNOT ladder folded in (buffer A) ----
        #pragma unroll
        for (int r = 0; r < 16; ++r)
            bufA[swz((r << 8) | t)] = make_float2(re[r], im[r]);
        __syncthreads();
        #pragma unroll
        for (int r = 0; r < 16; ++r) {
            const float2 v = bufA[swz(gperm((t << 4) | r))];
            re[r] = v.x; im[r] = v.y;
        }

        // ping-pong for next layer
        float2* tmp = bufA; bufA = bufB; bufB = tmp;
    }

    // ---- measurement: |amplitude| ----
    float4* orow = reinterpret_cast<float4*>(out + (size_t)row * DIM);
    #pragma unroll
    for (int k = 0; k < 4; ++k) {
        float4 v;
        v.x = sqrtf(re[4 * k + 0] * re[4 * k + 0] + im[4 * k + 0] * im[4 * k + 0]);
        v.y = sqrtf(re[4 * k + 1] * re[4 * k + 1] + im[4 * k + 1] * im[4 * k + 1]);
        v.z = sqrtf(re[4 * k + 2] * re[4 * k + 2] + im[4 * k + 2] * im[4 * k + 2]);
        v.w = sqrtf(re[4 * k + 3] * re[4 * k + 3] + im[4 * k + 3] * im[4 * k + 3]);
        orow[tid * 4 + k] = v;
    }
}

extern "C" void kernel_launch(void* const* d_in, const int* in_sizes, int n_in,
                              void* d_out, int out_size) {
    const float* input = (const float*)d_in[0];
    const float* ax    = (const float*)d_in[1];
    const float* ay    = (const float*)d_in[2];
    const float* az    = (const float*)d_in[3];
    float* out = (float*)d_out;
    const int rows = in_sizes[0] / DIM;
    const int smem = 2 * DIM * sizeof(float2);  // 64 KB ping-pong
    cudaFuncSetAttribute(qsim_kernel, cudaFuncAttributeMaxDynamicSharedMemorySize, smem);
    qsim_kernel<<<rows, NTHREADS, smem>>>(input, ax, ay, az, out);
}